// round 16
// baseline (speedup 1.0000x reference)
#include <cuda_runtime.h>

typedef unsigned long long u64;

__device__ float g_agg[1024 * 64 * 16];    // raw edge aggregation (4 MB)
__device__ float g_nr [1024 * 64 * 128];   // nodes @ W_r_bot + b_r (32 MB)
__device__ float g_Wnb[64 * 64];
__device__ float g_Weu[16 * 64];
__device__ float g_cu [64];
__device__ unsigned g_ctr;

__device__ __forceinline__ u64 pk2(float lo, float hi) {
    u64 r; asm("mov.b64 %0, {%1, %2};" : "=l"(r) : "f"(lo), "f"(hi)); return r;
}
__device__ __forceinline__ void fma2(u64 &d, u64 a, u64 b) {
    asm("fma.rn.f32x2 %0, %1, %2, %0;" : "+l"(d) : "l"(a), "l"(b));
}
__device__ __forceinline__ void add2(u64 &d, u64 a) {
    asm("add.rn.f32x2 %0, %0, %1;" : "+l"(d) : "l"(a));
}
__device__ __forceinline__ void up2(u64 v, float &lo, float &hi) {
    asm("mov.b64 {%0, %1}, %2;" : "=f"(lo), "=f"(hi) : "l"(v));
}

// ---------------------------------------------------------------------------
// k_pre: IDENTICAL to R15 (role-interleaved edge/nr/fold grid).
// ---------------------------------------------------------------------------
__global__ void __launch_bounds__(256)
k_pre(const int* __restrict__ adj, const float* __restrict__ edges,
      const float* __restrict__ nodes,
      const float* __restrict__ W_n, const float* __restrict__ W_e,
      const float* __restrict__ b_m, const float* __restrict__ W_u,
      const float* __restrict__ b_u,
      const float* __restrict__ W_r, const float* __restrict__ b_r)
{
    __shared__ float buf[12288];
    int bx = blockIdx.x, tid = threadIdx.x;
    int w = tid >> 5, lane = tid & 31;

    if (bx < 3072 && (bx % 3) < 2) {
        int e = (bx / 3) * 2 + (bx % 3);
        for (int t = 0; t < 4; t++) {
            int bv = e * 32 + t * 8 + w;
            const int*   arow = adj   + bv * 64;
            const float* erow = edges + (long)bv * 1024;
            float acc[16];
            #pragma unroll
            for (int q = 0; q < 16; q++) acc[q] = 0.f;
            #pragma unroll
            for (int s = 0; s < 2; s++) {
                int u = lane + s * 32;
                if (arow[u] != 0) {
                    const float4* e4 = (const float4*)(erow + u * 16);
                    float4 x0 = e4[0], x1 = e4[1], x2 = e4[2], x3 = e4[3];
                    acc[0] += x0.x;  acc[1] += x0.y;  acc[2]  += x0.z;  acc[3]  += x0.w;
                    acc[4] += x1.x;  acc[5] += x1.y;  acc[6]  += x1.z;  acc[7]  += x1.w;
                    acc[8] += x2.x;  acc[9] += x2.y;  acc[10] += x2.z;  acc[11] += x2.w;
                    acc[12]+= x3.x;  acc[13]+= x3.y;  acc[14] += x3.z;  acc[15] += x3.w;
                }
            }
            #pragma unroll
            for (int off = 16; off > 0; off >>= 1)
                #pragma unroll
                for (int q = 0; q < 16; q++)
                    acc[q] += __shfl_xor_sync(0xffffffffu, acc[q], off);
            if (lane == 0) {
                float4* dst = (float4*)(g_agg + bv * 16);
                dst[0] = make_float4(acc[0],  acc[1],  acc[2],  acc[3]);
                dst[1] = make_float4(acc[4],  acc[5],  acc[6],  acc[7]);
                dst[2] = make_float4(acc[8],  acc[9],  acc[10], acc[11]);
                dst[3] = make_float4(acc[12], acc[13], acc[14], acc[15]);
            }
        }
    } else if (bx < 3072) {
        int b = bx / 3;
        float* s_Wr = buf;
        float* s_nd = buf + 8192;
        for (int i4 = tid; i4 < 2048; i4 += 256)
            *(float4*)&s_Wr[i4 * 4] = *(const float4*)&W_r[8192 + i4 * 4];
        for (int i4 = tid; i4 < 1024; i4 += 256)
            *(float4*)&s_nd[i4 * 4] = *(const float4*)&nodes[(long)b * 4096 + i4 * 4];
        __syncthreads();

        const int rx = tid & 31, ry = tid >> 5;
        const int o0 = rx * 4, v0r = ry * 8;
        u64 acc[8][2];
        {
            ulonglong2 br = *(const ulonglong2*)&b_r[o0];
            #pragma unroll
            for (int vv = 0; vv < 8; vv++) { acc[vv][0] = br.x; acc[vv][1] = br.y; }
        }
        #pragma unroll 2
        for (int k = 0; k < 64; k++) {
            ulonglong2 q = *(const ulonglong2*)&s_Wr[k * 128 + o0];
            #pragma unroll
            for (int vv = 0; vv < 8; vv++) {
                float nv = s_nd[(v0r + vv) * 64 + k];
                u64 np = pk2(nv, nv);
                fma2(acc[vv][0], np, q.x); fma2(acc[vv][1], np, q.y);
            }
        }
        #pragma unroll
        for (int vv = 0; vv < 8; vv++) {
            ulonglong2 o; o.x = acc[vv][0]; o.y = acc[vv][1];
            *(ulonglong2*)&g_nr[(long)(b * 64 + v0r + vv) * 128 + o0] = o;
        }
    } else {
        float* s_Wu = buf;
        float* s_A  = buf + 8192;
        for (int i = tid; i < 8192; i += 256) s_Wu[i] = W_u[4096 + i];
        if (bx < 3080) {
            int r0 = (bx - 3072) * 8;
            for (int i = tid; i < 1024; i += 256) s_A[i] = W_n[r0 * 128 + i];
            __syncthreads();
            int g = tid & 63, r = tid >> 6;
            for (int rr = r; rr < 8; rr += 4) {
                float acc = 0.f;
                #pragma unroll 8
                for (int m = 0; m < 128; m++)
                    acc += s_A[rr * 128 + m] * s_Wu[m * 64 + g];
                g_Wnb[(r0 + rr) * 64 + g] = acc;
            }
        } else {
            if (tid == 0) g_ctr = 0u;
            for (int i = tid; i < 2048; i += 256) s_A[i] = W_e[i];
            __syncthreads();
            int g = tid & 63, r = tid >> 6;
            for (int rr = r; rr < 16; rr += 4) {
                float acc = 0.f;
                #pragma unroll 8
                for (int m = 0; m < 128; m++)
                    acc += s_A[rr * 128 + m] * s_Wu[m * 64 + g];
                g_Weu[rr * 64 + g] = acc;
            }
            if (tid < 64) {
                float acc = b_u[tid];
                #pragma unroll 8
                for (int m = 0; m < 128; m++)
                    acc += b_m[m] * s_Wu[m * 64 + tid];
                g_cu[tid] = acc;
            }
        }
    }
}

// ---------------------------------------------------------------------------
// k_mpnn: R15 structure; pass loops rewritten with warp-specialized G/T split.
// ---------------------------------------------------------------------------
#define SMEM_BYTES (25408 * 4)

__global__ void __launch_bounds__(256, 2)
k_mpnn(const int* __restrict__ adj, const float* __restrict__ nodes,
       const float* __restrict__ W_u, const float* __restrict__ W_r,
       float* __restrict__ out)
{
    extern __shared__ float sm[];
    float* s_hT   = sm;
    float* s_W    = sm + 4352;
    float* s_aT   = sm + 12544;
    float* s_T    = sm + 16896;
    float* s_et   = sm + 20992;
    float* s_mask = sm + 25344;
    float* s_red  = s_W;
    __shared__ unsigned s_b;

    int tid = threadIdx.x;
    const int tx = tid & 15, ty = tid >> 4;     // staging/et2 map
    const int g0 = tx * 4,   v0 = ty * 4;
    const int rx = tid & 31, ry = tid >> 5;     // readout map
    const int o0 = rx * 4,   v0r = ry * 8;
    // pass map: warp-specialized 4v x 8g tiles
    const int grp = tid >> 7;                   // 0 = G-group, 1 = T-group
    const int gt  = tid & 127;
    const int pg0 = (gt & 7) * 8, pv0 = (gt >> 3) * 4;
    const int wb  = pg0 + (grp << 6);           // weight base: Wut | Wnb

    while (true) {
        if (tid == 0) s_b = atomicAdd(&g_ctr, 1u);
        __syncthreads();
        unsigned b = s_b;
        if (b >= 1024u) break;

        const float* nb = nodes + b * 4096;
        const int*   ab = adj   + b * 4096;
        for (int i4 = tid; i4 < 1024; i4 += 256) {
            int v = i4 >> 4, f = (i4 & 15) * 4;
            float4 hv = *(const float4*)&nb[v * 64 + f];
            s_hT[(f + 0) * 68 + v] = hv.x;
            s_hT[(f + 1) * 68 + v] = hv.y;
            s_hT[(f + 2) * 68 + v] = hv.z;
            s_hT[(f + 3) * 68 + v] = hv.w;
            int4 a4 = *(const int4*)&ab[v * 64 + f];
            s_aT[(f + 0) * 68 + v] = (float)a4.x;
            s_aT[(f + 1) * 68 + v] = (float)a4.y;
            s_aT[(f + 2) * 68 + v] = (float)a4.z;
            s_aT[(f + 3) * 68 + v] = (float)a4.w;
        }
        for (int i4 = tid; i4 < 2048; i4 += 256) {
            int f = i4 >> 5, gq = (i4 & 31) * 4;
            *(float4*)&s_W[f * 128 + gq] = (gq < 64)
                ? *(const float4*)&W_u[f * 64 + gq]
                : *(const float4*)&g_Wnb[f * 64 + gq - 64];
        }
        for (int i = tid; i < 1024; i += 256) {
            s_T[i]        = g_agg[(long)b * 1024 + i];
            s_T[1024 + i] = g_Weu[i];
        }
        if (tid < 64) s_T[2048 + tid] = g_cu[tid];
        __syncthreads();

        if (tid < 64) {
            float s = 0.f;
            #pragma unroll 8
            for (int u = 0; u < 64; u++) s += s_aT[u * 68 + tid];
            s_mask[tid] = (s > 0.f) ? 1.f : 0.f;
        }
        {   // et2[v][g] = cu[g] + agg[v] @ Weu[:,g]
            float4 cu4 = *(const float4*)&s_T[2048 + g0];
            #pragma unroll
            for (int i = 0; i < 4; i++) {
                float e0 = cu4.x, e1 = cu4.y, e2 = cu4.z, e3 = cu4.w;
                #pragma unroll
                for (int e = 0; e < 16; e++) {
                    float a = s_T[(v0 + i) * 16 + e];
                    float4 u4 = *(const float4*)&s_T[1024 + e * 64 + g0];
                    e0 += a * u4.x; e1 += a * u4.y; e2 += a * u4.z; e3 += a * u4.w;
                }
                *(float4*)&s_et[(v0 + i) * 64 + g0] = make_float4(e0, e1, e2, e3);
            }
        }
        __syncthreads();
        float mkp[4];
        #pragma unroll
        for (int i = 0; i < 4; i++) mkp[i] = s_mask[pv0 + i];

        // ---- 4 message passes: warp-specialized ----
        for (int pass = 0; pass < 4; pass++) {
            u64 R[4][4];
            #pragma unroll
            for (int i = 0; i < 4; i++)
                #pragma unroll
                for (int j = 0; j < 4; j++) R[i][j] = 0ull;

            // Phase A: grp0: R = h@Wut ; grp1: R = h@Wnb
            #pragma unroll 4
            for (int f = 0; f < 64; f++) {
                float4 hv = *(const float4*)&s_hT[f * 68 + pv0];
                ulonglong2 wa = *(const ulonglong2*)&s_W[f * 128 + wb];
                ulonglong2 wc = *(const ulonglong2*)&s_W[f * 128 + wb + 4];
                u64 hp;
                hp = pk2(hv.x, hv.x);
                fma2(R[0][0], hp, wa.x); fma2(R[0][1], hp, wa.y);
                fma2(R[0][2], hp, wc.x); fma2(R[0][3], hp, wc.y);
                hp = pk2(hv.y, hv.y);
                fma2(R[1][0], hp, wa.x); fma2(R[1][1], hp, wa.y);
                fma2(R[1][2], hp, wc.x); fma2(R[1][3], hp, wc.y);
                hp = pk2(hv.z, hv.z);
                fma2(R[2][0], hp, wa.x); fma2(R[2][1], hp, wa.y);
                fma2(R[2][2], hp, wc.x); fma2(R[2][3], hp, wc.y);
                hp = pk2(hv.w, hv.w);
                fma2(R[3][0], hp, wa.x); fma2(R[3][1], hp, wa.y);
                fma2(R[3][2], hp, wc.x); fma2(R[3][3], hp, wc.y);
            }
            if (grp) {   // T-group: publish T
                #pragma unroll
                for (int i = 0; i < 4; i++) {
                    ulonglong2 p;
                    p.x = R[i][0]; p.y = R[i][1];
                    *(ulonglong2*)&s_T[(pv0 + i) * 64 + pg0] = p;
                    p.x = R[i][2]; p.y = R[i][3];
                    *(ulonglong2*)&s_T[(pv0 + i) * 64 + pg0 + 4] = p;
                }
            }
            __syncthreads();

            if (!grp) {  // G-group: R += adj @ T, then epilogue
                #pragma unroll 4
                for (int u = 0; u < 64; u++) {
                    ulonglong2 t0 = *(const ulonglong2*)&s_T[u * 64 + pg0];
                    ulonglong2 t1 = *(const ulonglong2*)&s_T[u * 64 + pg0 + 4];
                    float4 av = *(const float4*)&s_aT[u * 68 + pv0];
                    u64 a;
                    a = pk2(av.x, av.x);
                    fma2(R[0][0], a, t0.x); fma2(R[0][1], a, t0.y);
                    fma2(R[0][2], a, t1.x); fma2(R[0][3], a, t1.y);
                    a = pk2(av.y, av.y);
                    fma2(R[1][0], a, t0.x); fma2(R[1][1], a, t0.y);
                    fma2(R[1][2], a, t1.x); fma2(R[1][3], a, t1.y);
                    a = pk2(av.z, av.z);
                    fma2(R[2][0], a, t0.x); fma2(R[2][1], a, t0.y);
                    fma2(R[2][2], a, t1.x); fma2(R[2][3], a, t1.y);
                    a = pk2(av.w, av.w);
                    fma2(R[3][0], a, t0.x); fma2(R[3][1], a, t0.y);
                    fma2(R[3][2], a, t1.x); fma2(R[3][3], a, t1.y);
                }
                #pragma unroll
                for (int i = 0; i < 4; i++) {
                    if (mkp[i] != 0.f) {
                        ulonglong2 e0 = *(const ulonglong2*)&s_et[(pv0 + i) * 64 + pg0];
                        ulonglong2 e1 = *(const ulonglong2*)&s_et[(pv0 + i) * 64 + pg0 + 4];
                        add2(R[i][0], e0.x); add2(R[i][1], e0.y);
                        add2(R[i][2], e1.x); add2(R[i][3], e1.y);
                        float x0, x1, x2, x3, x4, x5, x6, x7;
                        up2(R[i][0], x0, x1); up2(R[i][1], x2, x3);
                        up2(R[i][2], x4, x5); up2(R[i][3], x6, x7);
                        s_hT[(pg0 + 0) * 68 + pv0 + i] = fmaxf(x0, 0.f);
                        s_hT[(pg0 + 1) * 68 + pv0 + i] = fmaxf(x1, 0.f);
                        s_hT[(pg0 + 2) * 68 + pv0 + i] = fmaxf(x2, 0.f);
                        s_hT[(pg0 + 3) * 68 + pv0 + i] = fmaxf(x3, 0.f);
                        s_hT[(pg0 + 4) * 68 + pv0 + i] = fmaxf(x4, 0.f);
                        s_hT[(pg0 + 5) * 68 + pv0 + i] = fmaxf(x5, 0.f);
                        s_hT[(pg0 + 6) * 68 + pv0 + i] = fmaxf(x6, 0.f);
                        s_hT[(pg0 + 7) * 68 + pv0 + i] = fmaxf(x7, 0.f);
                    }
                }
            }
            __syncthreads();
        }

        // ---- readout (identical to R15): out = sum_v mask*relu(h@Wr_top + nr)
        for (int i4 = tid; i4 < 2048; i4 += 256)
            *(float4*)&s_W[i4 * 4] = *(const float4*)&W_r[i4 * 4];
        __syncthreads();

        u64 acc[8][2];
        #pragma unroll
        for (int vv = 0; vv < 8; vv++) {
            float4 f = __ldcg((const float4*)&g_nr[(long)(b * 64 + v0r + vv) * 128 + o0]);
            acc[vv][0] = pk2(f.x, f.y);
            acc[vv][1] = pk2(f.z, f.w);
        }
        #pragma unroll 2
        for (int k = 0; k < 64; k++) {
            ulonglong2 q = *(const ulonglong2*)&s_W[k * 128 + o0];
            float4 h0 = *(const float4*)&s_hT[k * 68 + v0r];
            float4 h1 = *(const float4*)&s_hT[k * 68 + v0r + 4];
            u64 hp;
            hp = pk2(h0.x, h0.x); fma2(acc[0][0], hp, q.x); fma2(acc[0][1], hp, q.y);
            hp = pk2(h0.y, h0.y); fma2(acc[1][0], hp, q.x); fma2(acc[1][1], hp, q.y);
            hp = pk2(h0.z, h0.z); fma2(acc[2][0], hp, q.x); fma2(acc[2][1], hp, q.y);
            hp = pk2(h0.w, h0.w); fma2(acc[3][0], hp, q.x); fma2(acc[3][1], hp, q.y);
            hp = pk2(h1.x, h1.x); fma2(acc[4][0], hp, q.x); fma2(acc[4][1], hp, q.y);
            hp = pk2(h1.y, h1.y); fma2(acc[5][0], hp, q.x); fma2(acc[5][1], hp, q.y);
            hp = pk2(h1.z, h1.z); fma2(acc[6][0], hp, q.x); fma2(acc[6][1], hp, q.y);
            hp = pk2(h1.w, h1.w); fma2(acc[7][0], hp, q.x); fma2(acc[7][1], hp, q.y);
        }
        float oa[4] = {0.f, 0.f, 0.f, 0.f};
        #pragma unroll
        for (int vv = 0; vv < 8; vv++) {
            if (s_mask[v0r + vv] != 0.f) {
                float y0, y1, y2, y3;
                up2(acc[vv][0], y0, y1); up2(acc[vv][1], y2, y3);
                oa[0] += fmaxf(y0, 0.f); oa[1] += fmaxf(y1, 0.f);
                oa[2] += fmaxf(y2, 0.f); oa[3] += fmaxf(y3, 0.f);
            }
        }
        __syncthreads();
        *(float4*)&s_red[ry * 128 + o0] = make_float4(oa[0], oa[1], oa[2], oa[3]);
        __syncthreads();
        if (tid < 128) {
            float s = 0.f;
            #pragma unroll
            for (int t = 0; t < 8; t++) s += s_red[t * 128 + tid];
            out[b * 128 + tid] = s;
        }
        __syncthreads();
    }
}

// ---------------------------------------------------------------------------
extern "C" void kernel_launch(void* const* d_in, const int* in_sizes, int n_in,
                              void* d_out, int out_size)
{
    const int*   adj   = (const int*)  d_in[0];
    const float* nodes = (const float*)d_in[1];
    const float* edges = (const float*)d_in[2];
    const float* W_n   = (const float*)d_in[3];
    const float* W_e   = (const float*)d_in[4];
    const float* b_m   = (const float*)d_in[5];
    const float* W_u   = (const float*)d_in[6];
    const float* b_u   = (const float*)d_in[7];
    const float* W_r   = (const float*)d_in[8];
    const float* b_r   = (const float*)d_in[9];
    float* out = (float*)d_out;

    cudaFuncSetAttribute(k_mpnn, cudaFuncAttributeMaxDynamicSharedMemorySize,
                         SMEM_BYTES);

    k_pre<<<3081, 256>>>(adj, edges, nodes, W_n, W_e, b_m, W_u, b_u, W_r, b_r);
    k_mpnn<<<296, 256, SMEM_BYTES>>>(adj, nodes, W_u, W_r, out);
}

// round 17
// speedup vs baseline: 1.2477x; 1.2477x over previous
#include <cuda_runtime.h>

typedef unsigned long long u64;

__device__ float g_agg[1024 * 64 * 16];    // raw edge aggregation (4 MB)
__device__ float g_nr [1024 * 64 * 128];   // nodes @ W_r_bot + b_r (32 MB)
__device__ float g_Wnb[64 * 64];
__device__ float g_Weu[16 * 64];
__device__ float g_cu [64];
__device__ unsigned g_ctr;

__device__ __forceinline__ u64 pk2(float lo, float hi) {
    u64 r; asm("mov.b64 %0, {%1, %2};" : "=l"(r) : "f"(lo), "f"(hi)); return r;
}
__device__ __forceinline__ void fma2(u64 &d, u64 a, u64 b) {
    asm("fma.rn.f32x2 %0, %1, %2, %0;" : "+l"(d) : "l"(a), "l"(b));
}
__device__ __forceinline__ void add2(u64 &d, u64 a) {
    asm("add.rn.f32x2 %0, %0, %1;" : "+l"(d) : "l"(a));
}
__device__ __forceinline__ void up2(u64 v, float &lo, float &hi) {
    asm("mov.b64 {%0, %1}, %2;" : "=f"(lo), "=f"(hi) : "l"(v));
}

// ---------------------------------------------------------------------------
// k_pre, role-interleaved grid (2569 blocks):
//   bx < 2560, bx%5<4  : edge aggregation (e = (bx/5)*4 + bx%5)
//   bx < 2560, bx%5==4 : nr block for batch PAIR p = bx/5 (2 batches)
//   2560..2568         : weight folds + counter reset
// ---------------------------------------------------------------------------
__global__ void __launch_bounds__(256)
k_pre(const int* __restrict__ adj, const float* __restrict__ edges,
      const float* __restrict__ nodes,
      const float* __restrict__ W_n, const float* __restrict__ W_e,
      const float* __restrict__ b_m, const float* __restrict__ W_u,
      const float* __restrict__ b_u,
      const float* __restrict__ W_r, const float* __restrict__ b_r)
{
    __shared__ float buf[12288];   // 48 KB
    int bx = blockIdx.x, tid = threadIdx.x;
    int w = tid >> 5, lane = tid & 31;

    if (bx < 2560 && (bx % 5) < 4) {
        // ---- edge aggregation (R6-proven inner) ----
        int e = (bx / 5) * 4 + (bx % 5);
        for (int t = 0; t < 4; t++) {
            int bv = e * 32 + t * 8 + w;
            const int*   arow = adj   + bv * 64;
            const float* erow = edges + (long)bv * 1024;
            float acc[16];
            #pragma unroll
            for (int q = 0; q < 16; q++) acc[q] = 0.f;
            #pragma unroll
            for (int s = 0; s < 2; s++) {
                int u = lane + s * 32;
                if (arow[u] != 0) {
                    const float4* e4 = (const float4*)(erow + u * 16);
                    float4 x0 = e4[0], x1 = e4[1], x2 = e4[2], x3 = e4[3];
                    acc[0] += x0.x;  acc[1] += x0.y;  acc[2]  += x0.z;  acc[3]  += x0.w;
                    acc[4] += x1.x;  acc[5] += x1.y;  acc[6]  += x1.z;  acc[7]  += x1.w;
                    acc[8] += x2.x;  acc[9] += x2.y;  acc[10] += x2.z;  acc[11] += x2.w;
                    acc[12]+= x3.x;  acc[13]+= x3.y;  acc[14] += x3.z;  acc[15] += x3.w;
                }
            }
            #pragma unroll
            for (int off = 16; off > 0; off >>= 1)
                #pragma unroll
                for (int q = 0; q < 16; q++)
                    acc[q] += __shfl_xor_sync(0xffffffffu, acc[q], off);
            if (lane == 0) {
                float4* dst = (float4*)(g_agg + bv * 16);
                dst[0] = make_float4(acc[0],  acc[1],  acc[2],  acc[3]);
                dst[1] = make_float4(acc[4],  acc[5],  acc[6],  acc[7]);
                dst[2] = make_float4(acc[8],  acc[9],  acc[10], acc[11]);
                dst[3] = make_float4(acc[12], acc[13], acc[14], acc[15]);
            }
        }
    } else if (bx < 2560) {
        // ---- nr block: TWO batches, W_r staged once ----
        int p = bx / 5;
        float* s_Wr = buf;           // 8192 : W_r rows 64..127
        float* s_nd = buf + 8192;    // 4096 : nodes[b]
        for (int i4 = tid; i4 < 2048; i4 += 256)
            *(float4*)&s_Wr[i4 * 4] = *(const float4*)&W_r[8192 + i4 * 4];

        const int rx = tid & 31, ry = tid >> 5;
        const int o0 = rx * 4, v0r = ry * 8;
        for (int half = 0; half < 2; half++) {
            int b = p * 2 + half;
            __syncthreads();
            for (int i4 = tid; i4 < 1024; i4 += 256)
                *(float4*)&s_nd[i4 * 4] = *(const float4*)&nodes[(long)b * 4096 + i4 * 4];
            __syncthreads();

            u64 acc[8][2];
            {
                ulonglong2 br = *(const ulonglong2*)&b_r[o0];
                #pragma unroll
                for (int vv = 0; vv < 8; vv++) { acc[vv][0] = br.x; acc[vv][1] = br.y; }
            }
            #pragma unroll 2
            for (int k = 0; k < 64; k++) {
                ulonglong2 q = *(const ulonglong2*)&s_Wr[k * 128 + o0];
                #pragma unroll
                for (int vv = 0; vv < 8; vv++) {
                    float nv = s_nd[(v0r + vv) * 64 + k];
                    u64 np = pk2(nv, nv);
                    fma2(acc[vv][0], np, q.x); fma2(acc[vv][1], np, q.y);
                }
            }
            #pragma unroll
            for (int vv = 0; vv < 8; vv++) {
                ulonglong2 o; o.x = acc[vv][0]; o.y = acc[vv][1];
                *(ulonglong2*)&g_nr[(long)(b * 64 + v0r + vv) * 128 + o0] = o;
            }
        }
    } else {
        // ---- fold blocks ----
        float* s_Wu = buf;
        float* s_A  = buf + 8192;
        for (int i = tid; i < 8192; i += 256) s_Wu[i] = W_u[4096 + i];
        if (bx < 2568) {
            int r0 = (bx - 2560) * 8;
            for (int i = tid; i < 1024; i += 256) s_A[i] = W_n[r0 * 128 + i];
            __syncthreads();
            int g = tid & 63, r = tid >> 6;
            for (int rr = r; rr < 8; rr += 4) {
                float acc = 0.f;
                #pragma unroll 8
                for (int m = 0; m < 128; m++)
                    acc += s_A[rr * 128 + m] * s_Wu[m * 64 + g];
                g_Wnb[(r0 + rr) * 64 + g] = acc;
            }
        } else {
            if (tid == 0) g_ctr = 0u;
            for (int i = tid; i < 2048; i += 256) s_A[i] = W_e[i];
            __syncthreads();
            int g = tid & 63, r = tid >> 6;
            for (int rr = r; rr < 16; rr += 4) {
                float acc = 0.f;
                #pragma unroll 8
                for (int m = 0; m < 128; m++)
                    acc += s_A[rr * 128 + m] * s_Wu[m * 64 + g];
                g_Weu[rr * 64 + g] = acc;
            }
            if (tid < 64) {
                float acc = b_u[tid];
                #pragma unroll 8
                for (int m = 0; m < 128; m++)
                    acc += b_m[m] * s_Wu[m * 64 + tid];
                g_cu[tid] = acc;
            }
        }
    }
}

// ---------------------------------------------------------------------------
// k_mpnn: R15 pass core; s_W (Wu|Wnb) now staged ONCE per CTA (persistent),
// readout W_r overlays dead aT+T region, reduction overlays et.
// smem (floats): s_W[0,8192) persist | s_hT[8192,12544) | s_aT[12544,16896)
//                s_T[16896,20992) | s_et[20992,25088) | s_mask[25088,25152)
// readout: s_Wr = sm+12544 (spans aT+T, 8448>=8192), s_red = s_et
// total 25152 floats = 100608 B -> 2 CTAs/SM
// ---------------------------------------------------------------------------
#define SMEM_BYTES (25152 * 4)

__global__ void __launch_bounds__(256, 2)
k_mpnn(const int* __restrict__ adj, const float* __restrict__ nodes,
       const float* __restrict__ W_u, const float* __restrict__ W_r,
       float* __restrict__ out)
{
    extern __shared__ float sm[];
    float* s_W    = sm;
    float* s_hT   = sm + 8192;
    float* s_aT   = sm + 12544;
    float* s_T    = sm + 16896;
    float* s_et   = sm + 20992;
    float* s_mask = sm + 25088;
    float* s_Wr   = sm + 12544;   // readout overlay
    float* s_red  = s_et;         // readout overlay
    __shared__ unsigned s_b;

    int tid = threadIdx.x;
    const int tx = tid & 15, ty = tid >> 4;
    const int g0 = tx * 4,   v0 = ty * 4;
    const int rx = tid & 31, ry = tid >> 5;
    const int o0 = rx * 4,   v0r = ry * 8;

    // ---- stage weights ONCE (k_pre completed before this kernel) ----
    for (int i4 = tid; i4 < 2048; i4 += 256) {
        int f = i4 >> 5, gq = (i4 & 31) * 4;
        *(float4*)&s_W[f * 128 + gq] = (gq < 64)
            ? *(const float4*)&W_u[f * 64 + gq]
            : *(const float4*)&g_Wnb[f * 64 + gq - 64];
    }
    __syncthreads();

    while (true) {
        if (tid == 0) s_b = atomicAdd(&g_ctr, 1u);
        __syncthreads();
        unsigned b = s_b;
        if (b >= 1024u) break;

        const float* nb = nodes + b * 4096;
        const int*   ab = adj   + b * 4096;
        for (int i4 = tid; i4 < 1024; i4 += 256) {
            int v = i4 >> 4, f = (i4 & 15) * 4;
            float4 hv = *(const float4*)&nb[v * 64 + f];
            s_hT[(f + 0) * 68 + v] = hv.x;
            s_hT[(f + 1) * 68 + v] = hv.y;
            s_hT[(f + 2) * 68 + v] = hv.z;
            s_hT[(f + 3) * 68 + v] = hv.w;
            int4 a4 = *(const int4*)&ab[v * 64 + f];
            s_aT[(f + 0) * 68 + v] = (float)a4.x;
            s_aT[(f + 1) * 68 + v] = (float)a4.y;
            s_aT[(f + 2) * 68 + v] = (float)a4.z;
            s_aT[(f + 3) * 68 + v] = (float)a4.w;
        }
        for (int i = tid; i < 1024; i += 256) {
            s_T[i]        = g_agg[(long)b * 1024 + i];
            s_T[1024 + i] = g_Weu[i];
        }
        if (tid < 64) s_T[2048 + tid] = g_cu[tid];
        __syncthreads();

        if (tid < 64) {
            float s = 0.f;
            #pragma unroll 8
            for (int u = 0; u < 64; u++) s += s_aT[u * 68 + tid];
            s_mask[tid] = (s > 0.f) ? 1.f : 0.f;
        }
        {   // et2[v][g] = cu[g] + agg[v] @ Weu[:,g]
            float4 cu4 = *(const float4*)&s_T[2048 + g0];
            #pragma unroll
            for (int i = 0; i < 4; i++) {
                float e0 = cu4.x, e1 = cu4.y, e2 = cu4.z, e3 = cu4.w;
                #pragma unroll
                for (int e = 0; e < 16; e++) {
                    float a = s_T[(v0 + i) * 16 + e];
                    float4 u4 = *(const float4*)&s_T[1024 + e * 64 + g0];
                    e0 += a * u4.x; e1 += a * u4.y; e2 += a * u4.z; e3 += a * u4.w;
                }
                *(float4*)&s_et[(v0 + i) * 64 + g0] = make_float4(e0, e1, e2, e3);
            }
        }
        __syncthreads();
        float mk[4];
        #pragma unroll
        for (int i = 0; i < 4; i++) mk[i] = s_mask[v0 + i];

        // ---- 4 message passes (R15 core, unchanged) ----
        for (int pass = 0; pass < 4; pass++) {
            u64 G[4][2], T[4][2];
            #pragma unroll
            for (int i = 0; i < 4; i++) {
                G[i][0] = 0ull; G[i][1] = 0ull;
                T[i][0] = 0ull; T[i][1] = 0ull;
            }
            #pragma unroll 4
            for (int f = 0; f < 64; f++) {
                ulonglong2 wg = *(const ulonglong2*)&s_W[f * 128 + g0];
                ulonglong2 wt = *(const ulonglong2*)&s_W[f * 128 + 64 + g0];
                float4 hv = *(const float4*)&s_hT[f * 68 + v0];
                u64 hp;
                hp = pk2(hv.x, hv.x);
                fma2(G[0][0], hp, wg.x); fma2(G[0][1], hp, wg.y);
                fma2(T[0][0], hp, wt.x); fma2(T[0][1], hp, wt.y);
                hp = pk2(hv.y, hv.y);
                fma2(G[1][0], hp, wg.x); fma2(G[1][1], hp, wg.y);
                fma2(T[1][0], hp, wt.x); fma2(T[1][1], hp, wt.y);
                hp = pk2(hv.z, hv.z);
                fma2(G[2][0], hp, wg.x); fma2(G[2][1], hp, wg.y);
                fma2(T[2][0], hp, wt.x); fma2(T[2][1], hp, wt.y);
                hp = pk2(hv.w, hv.w);
                fma2(G[3][0], hp, wg.x); fma2(G[3][1], hp, wg.y);
                fma2(T[3][0], hp, wt.x); fma2(T[3][1], hp, wt.y);
            }
            #pragma unroll
            for (int i = 0; i < 4; i++) {
                ulonglong2 tv; tv.x = T[i][0]; tv.y = T[i][1];
                *(ulonglong2*)&s_T[(v0 + i) * 64 + g0] = tv;
            }
            __syncthreads();

            u64 S[4][2];
            #pragma unroll
            for (int i = 0; i < 4; i++) { S[i][0] = 0ull; S[i][1] = 0ull; }
            #pragma unroll 4
            for (int u = 0; u < 64; u++) {
                ulonglong2 tp = *(const ulonglong2*)&s_T[u * 64 + g0];
                float4 av = *(const float4*)&s_aT[u * 68 + v0];
                u64 a;
                a = pk2(av.x, av.x); fma2(S[0][0], a, tp.x); fma2(S[0][1], a, tp.y);
                a = pk2(av.y, av.y); fma2(S[1][0], a, tp.x); fma2(S[1][1], a, tp.y);
                a = pk2(av.z, av.z); fma2(S[2][0], a, tp.x); fma2(S[2][1], a, tp.y);
                a = pk2(av.w, av.w); fma2(S[3][0], a, tp.x); fma2(S[3][1], a, tp.y);
            }
            float x[4][4];
            #pragma unroll
            for (int i = 0; i < 4; i++) {
                ulonglong2 e = *(const ulonglong2*)&s_et[(v0 + i) * 64 + g0];
                add2(G[i][0], S[i][0]); add2(G[i][1], S[i][1]);
                add2(G[i][0], e.x);     add2(G[i][1], e.y);
                up2(G[i][0], x[i][0], x[i][1]);
                up2(G[i][1], x[i][2], x[i][3]);
                x[i][0] = fmaxf(x[i][0], 0.f); x[i][1] = fmaxf(x[i][1], 0.f);
                x[i][2] = fmaxf(x[i][2], 0.f); x[i][3] = fmaxf(x[i][3], 0.f);
            }
            #pragma unroll
            for (int j = 0; j < 4; j++) {
                float4 old = *(const float4*)&s_hT[(g0 + j) * 68 + v0];
                float4 nv;
                nv.x = (mk[0] != 0.f) ? x[0][j] : old.x;
                nv.y = (mk[1] != 0.f) ? x[1][j] : old.y;
                nv.z = (mk[2] != 0.f) ? x[2][j] : old.z;
                nv.w = (mk[3] != 0.f) ? x[3][j] : old.w;
                *(float4*)&s_hT[(g0 + j) * 68 + v0] = nv;
            }
            __syncthreads();
        }

        // ---- readout: out[o] = sum_v mask * relu(h@Wr_top + nr) ----
        for (int i4 = tid; i4 < 2048; i4 += 256)
            *(float4*)&s_Wr[i4 * 4] = *(const float4*)&W_r[i4 * 4];   // Wr top
        __syncthreads();

        u64 acc[8][2];
        #pragma unroll
        for (int vv = 0; vv < 8; vv++) {
            float4 f = __ldcg((const float4*)&g_nr[(long)(b * 64 + v0r + vv) * 128 + o0]);
            acc[vv][0] = pk2(f.x, f.y);
            acc[vv][1] = pk2(f.z, f.w);
        }
        #pragma unroll 2
        for (int k = 0; k < 64; k++) {
            ulonglong2 q = *(const ulonglong2*)&s_Wr[k * 128 + o0];
            float4 h0 = *(const float4*)&s_hT[k * 68 + v0r];
            float4 h1 = *(const float4*)&s_hT[k * 68 + v0r + 4];
            u64 hp;
            hp = pk2(h0.x, h0.x); fma2(acc[0][0], hp, q.x); fma2(acc[0][1], hp, q.y);
            hp = pk2(h0.y, h0.y); fma2(acc[1][0], hp, q.x); fma2(acc[1][1], hp, q.y);
            hp = pk2(h0.z, h0.z); fma2(acc[2][0], hp, q.x); fma2(acc[2][1], hp, q.y);
            hp = pk2(h0.w, h0.w); fma2(acc[3][0], hp, q.x); fma2(acc[3][1], hp, q.y);
            hp = pk2(h1.x, h1.x); fma2(acc[4][0], hp, q.x); fma2(acc[4][1], hp, q.y);
            hp = pk2(h1.y, h1.y); fma2(acc[5][0], hp, q.x); fma2(acc[5][1], hp, q.y);
            hp = pk2(h1.z, h1.z); fma2(acc[6][0], hp, q.x); fma2(acc[6][1], hp, q.y);
            hp = pk2(h1.w, h1.w); fma2(acc[7][0], hp, q.x); fma2(acc[7][1], hp, q.y);
        }
        float oa[4] = {0.f, 0.f, 0.f, 0.f};
        #pragma unroll
        for (int vv = 0; vv < 8; vv++) {
            if (s_mask[v0r + vv] != 0.f) {
                float y0, y1, y2, y3;
                up2(acc[vv][0], y0, y1); up2(acc[vv][1], y2, y3);
                oa[0] += fmaxf(y0, 0.f); oa[1] += fmaxf(y1, 0.f);
                oa[2] += fmaxf(y2, 0.f); oa[3] += fmaxf(y3, 0.f);
            }
        }
        __syncthreads();
        *(float4*)&s_red[ry * 128 + o0] = make_float4(oa[0], oa[1], oa[2], oa[3]);
        __syncthreads();
        if (tid < 128) {
            float s = 0.f;
            #pragma unroll
            for (int t = 0; t < 8; t++) s += s_red[t * 128 + tid];
            out[b * 128 + tid] = s;
        }
        __syncthreads();
    }
}

// ---------------------------------------------------------------------------
extern "C" void kernel_launch(void* const* d_in, const int* in_sizes, int n_in,
                              void* d_out, int out_size)
{
    const int*   adj   = (const int*)  d_in[0];
    const float* nodes = (const float*)d_in[1];
    const float* edges = (const float*)d_in[2];
    const float* W_n   = (const float*)d_in[3];
    const float* W_e   = (const float*)d_in[4];
    const float* b_m   = (const float*)d_in[5];
    const float* W_u   = (const float*)d_in[6];
    const float* b_u   = (const float*)d_in[7];
    const float* W_r   = (const float*)d_in[8];
    const float* b_r   = (const float*)d_in[9];
    float* out = (float*)d_out;

    cudaFuncSetAttribute(k_mpnn, cudaFuncAttributeMaxDynamicSharedMemorySize,
                         SMEM_BYTES);

    k_pre<<<2569, 256>>>(adj, edges, nodes, W_n, W_e, b_m, W_u, b_u, W_r, b_r);
    k_mpnn<<<296, 256, SMEM_BYTES>>>(adj, nodes, W_u, W_r, out);
}